// round 15
// baseline (speedup 1.0000x reference)
#include <cuda_runtime.h>
#include <cuda_bf16.h>
#include <cstdint>

#define N_NODES 50000
#define E_EDGES 800000
#define DIM 128
#define NEG_INF_F __int_as_float(0xff800000)

#define SCAN_B 49
#define SCAN_T 1024
#define HIST_PER_T 16

// ---------------------------------------------------------------------------
// Static device scratch (zero-restored each call; graph-replay deterministic)
// ---------------------------------------------------------------------------
__device__ float g_agg[(size_t)N_NODES * DIM];   // GEMM1 input: (1+eps)x + maxagg
__device__ float g_h[(size_t)N_NODES * DIM];
__device__ int   g_is64;
__device__ int   g_cnt[N_NODES];
__device__ int   g_row[N_NODES + 1];
__device__ int   g_cur[N_NODES];
__device__ int   g_blksum[SCAN_B];
__device__ int   g_done1;
__device__ int   g_done2;
__device__ int2  g_edge[E_EDGES];

// ---------------------------------------------------------------------------
// Kernel 0: fused histogram + exclusive scan (unchanged)
// ---------------------------------------------------------------------------
__global__ void __launch_bounds__(SCAN_T, 1)
histscan_kernel(const int* __restrict__ ei32) {
    __shared__ int sh[SCAN_T];
    __shared__ int pre[SCAN_B];
    __shared__ int offset;
    __shared__ int any_nonzero;
    __shared__ int bar_ok;

    int t = threadIdx.x;
    int b = blockIdx.x;

    if (t == 0) any_nonzero = 0;
    __syncthreads();
    if (t < 256) {
        int k = t * 3000;
        if (ei32[2 * k + 1] != 0) atomicOr(&any_nonzero, 1);
    }
    __syncthreads();
    int is64 = any_nonzero ? 0 : 1;
    if (b == 0 && t == 0) g_is64 = is64;

    const long long* e64 = (const long long*)ei32;
    #pragma unroll
    for (int i = 0; i < HIST_PER_T; ++i) {
        int e = b * SCAN_T + t + i * (SCAN_B * SCAN_T);
        if (e < E_EDGES) {
            int src, dst;
            if (is64) {
                src = (int)e64[e];
                dst = (int)e64[(size_t)E_EDGES + e];
            } else {
                src = ei32[e];
                dst = ei32[(size_t)E_EDGES + e];
            }
            if ((unsigned)src < N_NODES && (unsigned)dst < N_NODES)
                atomicAdd(&g_cnt[dst], 1);
        }
    }

    __threadfence();
    __syncthreads();
    if (t == 0) {
        atomicAdd(&g_done1, 1);
        while (((volatile int*)&g_done1)[0] < SCAN_B) { }
        bar_ok = 1;
    }
    __syncthreads();
    (void)bar_ok;
    __threadfence();

    int idx = b * SCAN_T + t;
    int c = (idx < N_NODES) ? g_cnt[idx] : 0;
    if (idx < N_NODES) g_cnt[idx] = 0;
    sh[t] = c;
    __syncthreads();
    #pragma unroll
    for (int off = 1; off < SCAN_T; off <<= 1) {
        int v = (t >= off) ? sh[t - off] : 0;
        __syncthreads();
        sh[t] += v;
        __syncthreads();
    }
    int ex = sh[t] - c;
    if (t == SCAN_T - 1)
        ((volatile int*)g_blksum)[b] = sh[t] + 1;

    if (t < SCAN_B) {
        int v;
        do { v = ((volatile int*)g_blksum)[t]; } while (v == 0);
        pre[t] = v - 1;
    }
    __syncthreads();
    if (t == 0) {
        int s = 0;
        for (int i = 0; i < b; ++i) s += pre[i];
        offset = s;
    }
    __syncthreads();

    if (idx <= N_NODES) g_row[idx] = ex + offset;
    if (idx < N_NODES)  g_cur[idx] = 0;

    if (t == 0) {
        int old = atomicAdd(&g_done2, 1);
        if (old == SCAN_B - 1) {
            for (int i = 0; i < SCAN_B; ++i) g_blksum[i] = 0;
            g_done1 = 0;
            g_done2 = 0;
        }
    }
}

// ---------------------------------------------------------------------------
// Kernel 1: bucket edges by dst (unchanged)
// ---------------------------------------------------------------------------
__global__ void fill_kernel(const int* __restrict__ ei32,
                            const float* __restrict__ ew) {
    int e = blockIdx.x * blockDim.x + threadIdx.x;
    if (e >= E_EDGES) return;
    int src, dst;
    if (g_is64) {
        const long long* e64 = (const long long*)ei32;
        src = (int)e64[e];
        dst = (int)e64[(size_t)E_EDGES + e];
    } else {
        src = ei32[e];
        dst = ei32[(size_t)E_EDGES + e];
    }
    if ((unsigned)src >= N_NODES || (unsigned)dst >= N_NODES) return;
    int pos = g_row[dst] + atomicAdd(&g_cur[dst], 1);
    g_edge[pos] = make_int2(src, __float_as_int(ew[e]));
}

// ---------------------------------------------------------------------------
// Kernel 2: aggregate + fuse (unchanged)
// ---------------------------------------------------------------------------
__device__ __forceinline__ float4 max4w(float4 a, float4 v, float w) {
    a.x = fmaxf(a.x, v.x * w);
    a.y = fmaxf(a.y, v.y * w);
    a.z = fmaxf(a.z, v.z * w);
    a.w = fmaxf(a.w, v.w * w);
    return a;
}

__global__ void agg_kernel(const float* __restrict__ x,
                           const float* __restrict__ eps) {
    int warp = (blockIdx.x * blockDim.x + threadIdx.x) >> 5;
    if (warp >= N_NODES) return;
    int lane = threadIdx.x & 31;
    int beg = __ldg(&g_row[warp]);
    int end = __ldg(&g_row[warp + 1]);

    float4 acc = make_float4(NEG_INF_F, NEG_INF_F, NEG_INF_F, NEG_INF_F);
    int j = beg;
    for (; j + 8 <= end; j += 8) {
        int2 e[8];
        #pragma unroll
        for (int i = 0; i < 8; ++i) e[i] = __ldg(&g_edge[j + i]);
        float4 v[8];
        #pragma unroll
        for (int i = 0; i < 8; ++i)
            v[i] = __ldg(&((const float4*)(x + (size_t)e[i].x * DIM))[lane]);
        #pragma unroll
        for (int i = 0; i < 8; ++i)
            acc = max4w(acc, v[i], __int_as_float(e[i].y));
    }
    if (j + 4 <= end) {
        int2 e[4];
        #pragma unroll
        for (int i = 0; i < 4; ++i) e[i] = __ldg(&g_edge[j + i]);
        float4 v[4];
        #pragma unroll
        for (int i = 0; i < 4; ++i)
            v[i] = __ldg(&((const float4*)(x + (size_t)e[i].x * DIM))[lane]);
        #pragma unroll
        for (int i = 0; i < 4; ++i)
            acc = max4w(acc, v[i], __int_as_float(e[i].y));
        j += 4;
    }
    for (; j < end; ++j) {
        int2 ep = __ldg(&g_edge[j]);
        float4 v = __ldg(&((const float4*)(x + (size_t)ep.x * DIM))[lane]);
        acc = max4w(acc, v, __int_as_float(ep.y));
    }
    if (beg == end) acc = make_float4(0.f, 0.f, 0.f, 0.f);

    float s = 1.0f + __ldg(eps);
    float4 xv = __ldg(&((const float4*)(x + (size_t)warp * DIM))[lane]);
    acc.x = fmaf(s, xv.x, acc.x);
    acc.y = fmaf(s, xv.y, acc.y);
    acc.z = fmaf(s, xv.z, acc.z);
    acc.w = fmaf(s, xv.w, acc.w);
    ((float4*)(g_agg + (size_t)warp * DIM))[lane] = acc;
}

// ---------------------------------------------------------------------------
// Tensor-core GEMM via mma.sync (HMMA). OUT = act(A @ W^T + Bias).
// bf16x3 split: D = Ah*Wh + Al*Wh + Ah*Wl, fp32 accum in registers.
// CTA: 64x128 tile, 512 threads, warp grid 2(m) x 8(n); warp tile 32x16.
// Smem: A hi/lo (64 rows) + W hi/lo (128 rows) = 104448 B -> 2 CTA/SM,
// 32 warps/SM. LDA=136 padding -> conflict-free ldmatrix.
// ---------------------------------------------------------------------------
#define TC_T 512
#define BM_TC 64
#define LDA 136
#define A_TILE_B (BM_TC * LDA * 2)    // 17408 B
#define W_TILE_B (128 * LDA * 2)      // 34816 B
#define SM_AH 0
#define SM_AL (A_TILE_B)
#define SM_WH (2 * A_TILE_B)
#define SM_WL (2 * A_TILE_B + W_TILE_B)
#define SMEM_TC (2 * A_TILE_B + 2 * W_TILE_B)   // 104448 B

__device__ __forceinline__ uint32_t smem_u32(const void* p) {
    uint32_t a;
    asm("{ .reg .u64 t; cvta.to.shared.u64 t, %1; cvt.u32.u64 %0, t; }"
        : "=r"(a) : "l"(p));
    return a;
}
__device__ __forceinline__ void ldsm_x4(uint32_t* r, uint32_t addr) {
    asm volatile("ldmatrix.sync.aligned.m8n8.x4.shared.b16 {%0,%1,%2,%3}, [%4];"
                 : "=r"(r[0]), "=r"(r[1]), "=r"(r[2]), "=r"(r[3]) : "r"(addr));
}
__device__ __forceinline__ void ldsm_x2(uint32_t* r, uint32_t addr) {
    asm volatile("ldmatrix.sync.aligned.m8n8.x2.shared.b16 {%0,%1}, [%2];"
                 : "=r"(r[0]), "=r"(r[1]) : "r"(addr));
}
__device__ __forceinline__ void mma_bf16(float* d, const uint32_t* a,
                                         const uint32_t* b) {
    asm volatile(
        "mma.sync.aligned.m16n8k16.row.col.f32.bf16.bf16.f32 "
        "{%0,%1,%2,%3}, {%4,%5,%6,%7}, {%8,%9}, {%0,%1,%2,%3};"
        : "+f"(d[0]), "+f"(d[1]), "+f"(d[2]), "+f"(d[3])
        : "r"(a[0]), "r"(a[1]), "r"(a[2]), "r"(a[3]), "r"(b[0]), "r"(b[1]));
}
__device__ __forceinline__ void split2(float v0, float v1,
                                       uint32_t& hi2, uint32_t& lo2) {
    __nv_bfloat16 h0 = __float2bfloat16_rn(v0);
    __nv_bfloat16 h1 = __float2bfloat16_rn(v1);
    __nv_bfloat16 l0 = __float2bfloat16_rn(v0 - __bfloat162float(h0));
    __nv_bfloat16 l1 = __float2bfloat16_rn(v1 - __bfloat162float(h1));
    hi2 = (uint32_t)__bfloat16_as_ushort(h0) |
          ((uint32_t)__bfloat16_as_ushort(h1) << 16);
    lo2 = (uint32_t)__bfloat16_as_ushort(l0) |
          ((uint32_t)__bfloat16_as_ushort(l1) << 16);
}

template <bool LEAKY>
__global__ void __launch_bounds__(TC_T, 2)
mlp_gemm_mma_kernel(const float* __restrict__ A,
                    const float* __restrict__ W,
                    const float* __restrict__ Bias,
                    float* __restrict__ OUT) {
    extern __shared__ char smc[];
    const uint32_t sbase = smem_u32(smc);
    const int tid  = threadIdx.x;
    const int wid  = tid >> 5;
    const int lane = tid & 31;
    const int m0   = blockIdx.x * BM_TC;

    // ---- Stage A (hi/lo): 2048 float4 over 512 threads = 4 per thread ----
    for (int i = tid; i < BM_TC * 32; i += TC_T) {
        int row = i >> 5;
        int c4  = (i & 31) * 4;
        int m   = m0 + row;
        float4 v = (m < N_NODES)
                 ? __ldg((const float4*)(A + (size_t)m * DIM + c4))
                 : make_float4(0.f, 0.f, 0.f, 0.f);
        uint32_t h0, l0, h1, l1;
        split2(v.x, v.y, h0, l0);
        split2(v.z, v.w, h1, l1);
        uint32_t boff = (uint32_t)(row * LDA + c4) * 2u;
        *(uint2*)(smc + SM_AH + boff) = make_uint2(h0, h1);
        *(uint2*)(smc + SM_AL + boff) = make_uint2(l0, l1);
    }
    // ---- Stage W (hi/lo): 4096 float4 = 8 per thread ----
    for (int i = tid; i < 4096; i += TC_T) {
        int row = i >> 5;
        int c4  = (i & 31) * 4;
        float4 v = __ldg((const float4*)(W + (size_t)row * DIM + c4));
        uint32_t h0, l0, h1, l1;
        split2(v.x, v.y, h0, l0);
        split2(v.z, v.w, h1, l1);
        uint32_t boff = (uint32_t)(row * LDA + c4) * 2u;
        *(uint2*)(smc + SM_WH + boff) = make_uint2(h0, h1);
        *(uint2*)(smc + SM_WL + boff) = make_uint2(l0, l1);
    }
    __syncthreads();

    // ---- Warp tiling: 2(m) x 8(n); warp tile 32 rows x 16 cols ----
    const int wm = wid & 1;
    const int wn = wid >> 1;

    const int a_row = (lane & 7) + (lane & 8);        // 0..15
    const int a_col = (lane >> 4) * 8;                // 0 or 8
    const int b_row = (lane & 7);
    const int b_col = ((lane >> 3) & 1) * 8;

    float d[2][2][4];
    #pragma unroll
    for (int mt = 0; mt < 2; ++mt)
        #pragma unroll
        for (int nt = 0; nt < 2; ++nt)
            #pragma unroll
            for (int q = 0; q < 4; ++q) d[mt][nt][q] = 0.0f;

    #pragma unroll 1
    for (int pass = 0; pass < 3; ++pass) {
        const uint32_t abase = sbase + ((pass == 1) ? SM_AL : SM_AH);
        const uint32_t wbase = sbase + ((pass == 2) ? SM_WL : SM_WH);
        #pragma unroll 4
        for (int ks = 0; ks < 8; ++ks) {
            const int k0 = ks * 16;
            uint32_t af[2][4];
            #pragma unroll
            for (int mt = 0; mt < 2; ++mt) {
                uint32_t addr = abase +
                    (uint32_t)((wm * 32 + mt * 16 + a_row) * LDA + k0 + a_col) * 2u;
                ldsm_x4(af[mt], addr);
            }
            uint32_t bfr[2][2];
            #pragma unroll
            for (int nt = 0; nt < 2; ++nt) {
                uint32_t addr = wbase +
                    (uint32_t)((wn * 16 + nt * 8 + b_row) * LDA + k0 + b_col) * 2u;
                ldsm_x2(bfr[nt], addr);
            }
            #pragma unroll
            for (int mt = 0; mt < 2; ++mt)
                #pragma unroll
                for (int nt = 0; nt < 2; ++nt)
                    mma_bf16(d[mt][nt], af[mt], bfr[nt]);
        }
    }

    // ---- Epilogue: bias + LeakyReLU, store from fragments ----
    const int colbase = wn * 16;
    #pragma unroll
    for (int nt = 0; nt < 2; ++nt) {
        int c = colbase + nt * 8 + (lane & 3) * 2;
        float2 bs = __ldg((const float2*)&Bias[c]);
        #pragma unroll
        for (int mt = 0; mt < 2; ++mt) {
            int r0 = m0 + wm * 32 + mt * 16 + (lane >> 2);
            const float* dd = d[mt][nt];
            if (r0 < N_NODES) {
                float v0 = dd[0] + bs.x;
                float v1 = dd[1] + bs.y;
                if (LEAKY) {
                    v0 = (v0 >= 0.0f) ? v0 : 0.01f * v0;
                    v1 = (v1 >= 0.0f) ? v1 : 0.01f * v1;
                }
                *(float2*)(OUT + (size_t)r0 * DIM + c) = make_float2(v0, v1);
            }
            int r1 = r0 + 8;
            if (r1 < N_NODES) {
                float v2 = dd[2] + bs.x;
                float v3 = dd[3] + bs.y;
                if (LEAKY) {
                    v2 = (v2 >= 0.0f) ? v2 : 0.01f * v2;
                    v3 = (v3 >= 0.0f) ? v3 : 0.01f * v3;
                }
                *(float2*)(OUT + (size_t)r1 * DIM + c) = make_float2(v2, v3);
            }
        }
    }
}

// ---------------------------------------------------------------------------
// Launcher — order: histscan(0), fill(1), agg(2), gemm1(3) <- ncu, gemm2(4)
// ---------------------------------------------------------------------------
extern "C" void kernel_launch(void* const* d_in, const int* in_sizes, int n_in,
                              void* d_out, int out_size) {
    const float* x   = (const float*)d_in[0];
    const int*   ei  = (const int*)d_in[1];
    const float* ew  = (const float*)d_in[2];
    const float* w1  = (const float*)d_in[3];
    const float* b1  = (const float*)d_in[4];
    const float* w2  = (const float*)d_in[5];
    const float* b2  = (const float*)d_in[6];
    const float* eps = (const float*)d_in[7];
    float*       out = (float*)d_out;

    cudaFuncSetAttribute(mlp_gemm_mma_kernel<true>,
                         cudaFuncAttributeMaxDynamicSharedMemorySize, SMEM_TC);
    cudaFuncSetAttribute(mlp_gemm_mma_kernel<false>,
                         cudaFuncAttributeMaxDynamicSharedMemorySize, SMEM_TC);

    void *agg_p = nullptr, *h_p = nullptr;
    cudaGetSymbolAddress(&agg_p, g_agg);
    cudaGetSymbolAddress(&h_p,   g_h);
    float* agg = (float*)agg_p;
    float* h   = (float*)h_p;

    histscan_kernel<<<SCAN_B, SCAN_T>>>(ei);                         // 0
    fill_kernel<<<(E_EDGES + 255) / 256, 256>>>(ei, ew);             // 1
    agg_kernel<<<(N_NODES * 32 + 255) / 256, 256>>>(x, eps);         // 2

    {
        int blocks = (N_NODES + BM_TC - 1) / BM_TC;
        mlp_gemm_mma_kernel<true><<<blocks, TC_T, SMEM_TC>>>(        // 3 <- ncu
            agg, w1, b1, h);
        mlp_gemm_mma_kernel<false><<<blocks, TC_T, SMEM_TC>>>(       // 4
            h, w2, b2, out);
    }
}

// round 16
// speedup vs baseline: 1.0641x; 1.0641x over previous
#include <cuda_runtime.h>
#include <cuda_bf16.h>
#include <cstdint>

#define N_NODES 50000
#define E_EDGES 800000
#define DIM 128
#define NEG_INF_F __int_as_float(0xff800000)

#define SCAN_B 49
#define SCAN_T 1024
#define HIST_PER_T 16

// ---------------------------------------------------------------------------
// Static device scratch (zero-restored each call; graph-replay deterministic)
// ---------------------------------------------------------------------------
__device__ int   g_is64;
__device__ int   g_cnt[N_NODES];
__device__ int   g_row[N_NODES + 1];
__device__ int   g_cur[N_NODES];
__device__ int   g_blksum[SCAN_B];
__device__ int   g_done1;
__device__ int   g_done2;
__device__ int2  g_edge[E_EDGES];

// bf16 hi/lo operands (produced once per call; GEMMs do pure copies)
__device__ __nv_bfloat16 g_w1h[DIM * DIM], g_w1l[DIM * DIM];
__device__ __nv_bfloat16 g_w2h[DIM * DIM], g_w2l[DIM * DIM];
__device__ __nv_bfloat16 g_ah[(size_t)N_NODES * DIM], g_al[(size_t)N_NODES * DIM];
__device__ __nv_bfloat16 g_hh[(size_t)N_NODES * DIM], g_hl[(size_t)N_NODES * DIM];

// split fp32 pair -> packed bf16x2 hi and lo (residual)
__device__ __forceinline__ void split2(float v0, float v1,
                                       uint32_t& hi2, uint32_t& lo2) {
    __nv_bfloat16 h0 = __float2bfloat16_rn(v0);
    __nv_bfloat16 h1 = __float2bfloat16_rn(v1);
    __nv_bfloat16 l0 = __float2bfloat16_rn(v0 - __bfloat162float(h0));
    __nv_bfloat16 l1 = __float2bfloat16_rn(v1 - __bfloat162float(h1));
    hi2 = (uint32_t)__bfloat16_as_ushort(h0) |
          ((uint32_t)__bfloat16_as_ushort(h1) << 16);
    lo2 = (uint32_t)__bfloat16_as_ushort(l0) |
          ((uint32_t)__bfloat16_as_ushort(l1) << 16);
}

// ---------------------------------------------------------------------------
// Kernel 0: fused histogram + exclusive scan + W bf16-split
// ---------------------------------------------------------------------------
__global__ void __launch_bounds__(SCAN_T, 1)
histscan_kernel(const int* __restrict__ ei32,
                const float* __restrict__ w1,
                const float* __restrict__ w2) {
    __shared__ int sh[SCAN_T];
    __shared__ int pre[SCAN_B];
    __shared__ int offset;
    __shared__ int any_nonzero;
    __shared__ int bar_ok;

    int t = threadIdx.x;
    int b = blockIdx.x;

    // --- W split (one elem per thread; 32768 < 49*1024) ---
    {
        int g = b * SCAN_T + t;
        if (g < DIM * DIM) {
            float v = __ldg(&w1[g]);
            __nv_bfloat16 h = __float2bfloat16_rn(v);
            g_w1h[g] = h;
            g_w1l[g] = __float2bfloat16_rn(v - __bfloat162float(h));
        } else if (g < 2 * DIM * DIM) {
            int q = g - DIM * DIM;
            float v = __ldg(&w2[q]);
            __nv_bfloat16 h = __float2bfloat16_rn(v);
            g_w2h[q] = h;
            g_w2l[q] = __float2bfloat16_rn(v - __bfloat162float(h));
        }
    }

    if (t == 0) any_nonzero = 0;
    __syncthreads();
    if (t < 256) {
        int k = t * 3000;
        if (ei32[2 * k + 1] != 0) atomicOr(&any_nonzero, 1);
    }
    __syncthreads();
    int is64 = any_nonzero ? 0 : 1;
    if (b == 0 && t == 0) g_is64 = is64;

    const long long* e64 = (const long long*)ei32;
    #pragma unroll
    for (int i = 0; i < HIST_PER_T; ++i) {
        int e = b * SCAN_T + t + i * (SCAN_B * SCAN_T);
        if (e < E_EDGES) {
            int src, dst;
            if (is64) {
                src = (int)e64[e];
                dst = (int)e64[(size_t)E_EDGES + e];
            } else {
                src = ei32[e];
                dst = ei32[(size_t)E_EDGES + e];
            }
            if ((unsigned)src < N_NODES && (unsigned)dst < N_NODES)
                atomicAdd(&g_cnt[dst], 1);
        }
    }

    __threadfence();
    __syncthreads();
    if (t == 0) {
        atomicAdd(&g_done1, 1);
        while (((volatile int*)&g_done1)[0] < SCAN_B) { }
        bar_ok = 1;
    }
    __syncthreads();
    (void)bar_ok;
    __threadfence();

    int idx = b * SCAN_T + t;
    int c = (idx < N_NODES) ? g_cnt[idx] : 0;
    if (idx < N_NODES) g_cnt[idx] = 0;
    sh[t] = c;
    __syncthreads();
    #pragma unroll
    for (int off = 1; off < SCAN_T; off <<= 1) {
        int v = (t >= off) ? sh[t - off] : 0;
        __syncthreads();
        sh[t] += v;
        __syncthreads();
    }
    int ex = sh[t] - c;
    if (t == SCAN_T - 1)
        ((volatile int*)g_blksum)[b] = sh[t] + 1;

    if (t < SCAN_B) {
        int v;
        do { v = ((volatile int*)g_blksum)[t]; } while (v == 0);
        pre[t] = v - 1;
    }
    __syncthreads();
    if (t == 0) {
        int s = 0;
        for (int i = 0; i < b; ++i) s += pre[i];
        offset = s;
    }
    __syncthreads();

    if (idx <= N_NODES) g_row[idx] = ex + offset;
    if (idx < N_NODES)  g_cur[idx] = 0;

    if (t == 0) {
        int old = atomicAdd(&g_done2, 1);
        if (old == SCAN_B - 1) {
            for (int i = 0; i < SCAN_B; ++i) g_blksum[i] = 0;
            g_done1 = 0;
            g_done2 = 0;
        }
    }
}

// ---------------------------------------------------------------------------
// Kernel 1: bucket edges by dst (unchanged)
// ---------------------------------------------------------------------------
__global__ void fill_kernel(const int* __restrict__ ei32,
                            const float* __restrict__ ew) {
    int e = blockIdx.x * blockDim.x + threadIdx.x;
    if (e >= E_EDGES) return;
    int src, dst;
    if (g_is64) {
        const long long* e64 = (const long long*)ei32;
        src = (int)e64[e];
        dst = (int)e64[(size_t)E_EDGES + e];
    } else {
        src = ei32[e];
        dst = ei32[(size_t)E_EDGES + e];
    }
    if ((unsigned)src >= N_NODES || (unsigned)dst >= N_NODES) return;
    int pos = g_row[dst] + atomicAdd(&g_cur[dst], 1);
    g_edge[pos] = make_int2(src, __float_as_int(ew[e]));
}

// ---------------------------------------------------------------------------
// Kernel 2: aggregate + fuse; emits GEMM1 input as bf16 hi/lo.
// g_ah+g_al encode (1+eps)*x + maxagg (0 for isolated nodes).
// ---------------------------------------------------------------------------
__device__ __forceinline__ float4 max4w(float4 a, float4 v, float w) {
    a.x = fmaxf(a.x, v.x * w);
    a.y = fmaxf(a.y, v.y * w);
    a.z = fmaxf(a.z, v.z * w);
    a.w = fmaxf(a.w, v.w * w);
    return a;
}

__global__ void agg_kernel(const float* __restrict__ x,
                           const float* __restrict__ eps) {
    int warp = (blockIdx.x * blockDim.x + threadIdx.x) >> 5;
    if (warp >= N_NODES) return;
    int lane = threadIdx.x & 31;
    int beg = __ldg(&g_row[warp]);
    int end = __ldg(&g_row[warp + 1]);

    float4 acc = make_float4(NEG_INF_F, NEG_INF_F, NEG_INF_F, NEG_INF_F);
    int j = beg;
    for (; j + 8 <= end; j += 8) {
        int2 e[8];
        #pragma unroll
        for (int i = 0; i < 8; ++i) e[i] = __ldg(&g_edge[j + i]);
        float4 v[8];
        #pragma unroll
        for (int i = 0; i < 8; ++i)
            v[i] = __ldg(&((const float4*)(x + (size_t)e[i].x * DIM))[lane]);
        #pragma unroll
        for (int i = 0; i < 8; ++i)
            acc = max4w(acc, v[i], __int_as_float(e[i].y));
    }
    if (j + 4 <= end) {
        int2 e[4];
        #pragma unroll
        for (int i = 0; i < 4; ++i) e[i] = __ldg(&g_edge[j + i]);
        float4 v[4];
        #pragma unroll
        for (int i = 0; i < 4; ++i)
            v[i] = __ldg(&((const float4*)(x + (size_t)e[i].x * DIM))[lane]);
        #pragma unroll
        for (int i = 0; i < 4; ++i)
            acc = max4w(acc, v[i], __int_as_float(e[i].y));
        j += 4;
    }
    for (; j < end; ++j) {
        int2 ep = __ldg(&g_edge[j]);
        float4 v = __ldg(&((const float4*)(x + (size_t)ep.x * DIM))[lane]);
        acc = max4w(acc, v, __int_as_float(ep.y));
    }
    if (beg == end) acc = make_float4(0.f, 0.f, 0.f, 0.f);

    float s = 1.0f + __ldg(eps);
    float4 xv = __ldg(&((const float4*)(x + (size_t)warp * DIM))[lane]);
    acc.x = fmaf(s, xv.x, acc.x);
    acc.y = fmaf(s, xv.y, acc.y);
    acc.z = fmaf(s, xv.z, acc.z);
    acc.w = fmaf(s, xv.w, acc.w);

    uint32_t h01, l01, h23, l23;
    split2(acc.x, acc.y, h01, l01);
    split2(acc.z, acc.w, h23, l23);
    size_t base = (size_t)warp * DIM + lane * 4;
    *(uint2*)(g_ah + base) = make_uint2(h01, h23);
    *(uint2*)(g_al + base) = make_uint2(l01, l23);
}

// ---------------------------------------------------------------------------
// Tensor-core GEMM via mma.sync (HMMA). OUT = act(A @ W^T + Bias).
// Operands pre-split to bf16 hi/lo in global; staging = pure uint4 copy.
// CTA: 64x128 tile, 512 threads, warp grid 2(m) x 8(n); warp tile 32x16.
// Smem 104448 B -> 2 CTA/SM. LDA=136 padding -> conflict-free ldmatrix.
// SPLIT_OUT: epilogue emits bf16 hi/lo (for gemm1 -> gemm2 chain);
// otherwise fp32 to OUT.
// ---------------------------------------------------------------------------
#define TC_T 512
#define BM_TC 64
#define LDA 136
#define A_TILE_B (BM_TC * LDA * 2)    // 17408 B
#define W_TILE_B (128 * LDA * 2)      // 34816 B
#define SM_AH 0
#define SM_AL (A_TILE_B)
#define SM_WH (2 * A_TILE_B)
#define SM_WL (2 * A_TILE_B + W_TILE_B)
#define SMEM_TC (2 * A_TILE_B + 2 * W_TILE_B)   // 104448 B

__device__ __forceinline__ uint32_t smem_u32(const void* p) {
    uint32_t a;
    asm("{ .reg .u64 t; cvta.to.shared.u64 t, %1; cvt.u32.u64 %0, t; }"
        : "=r"(a) : "l"(p));
    return a;
}
__device__ __forceinline__ void ldsm_x4(uint32_t* r, uint32_t addr) {
    asm volatile("ldmatrix.sync.aligned.m8n8.x4.shared.b16 {%0,%1,%2,%3}, [%4];"
                 : "=r"(r[0]), "=r"(r[1]), "=r"(r[2]), "=r"(r[3]) : "r"(addr));
}
__device__ __forceinline__ void ldsm_x2(uint32_t* r, uint32_t addr) {
    asm volatile("ldmatrix.sync.aligned.m8n8.x2.shared.b16 {%0,%1}, [%2];"
                 : "=r"(r[0]), "=r"(r[1]) : "r"(addr));
}
__device__ __forceinline__ void mma_bf16(float* d, const uint32_t* a,
                                         const uint32_t* b) {
    asm volatile(
        "mma.sync.aligned.m16n8k16.row.col.f32.bf16.bf16.f32 "
        "{%0,%1,%2,%3}, {%4,%5,%6,%7}, {%8,%9}, {%0,%1,%2,%3};"
        : "+f"(d[0]), "+f"(d[1]), "+f"(d[2]), "+f"(d[3])
        : "r"(a[0]), "r"(a[1]), "r"(a[2]), "r"(a[3]), "r"(b[0]), "r"(b[1]));
}

template <bool LEAKY, bool SPLIT_OUT>
__global__ void __launch_bounds__(TC_T, 2)
mlp_gemm_mma_kernel(const __nv_bfloat16* __restrict__ Ah,
                    const __nv_bfloat16* __restrict__ Al,
                    const __nv_bfloat16* __restrict__ Wh,
                    const __nv_bfloat16* __restrict__ Wl,
                    const float* __restrict__ Bias,
                    float* __restrict__ OUT,
                    __nv_bfloat16* __restrict__ OUTh,
                    __nv_bfloat16* __restrict__ OUTl) {
    extern __shared__ char smc[];
    const uint32_t sbase = smem_u32(smc);
    const int tid  = threadIdx.x;
    const int wid  = tid >> 5;
    const int lane = tid & 31;
    const int m0   = blockIdx.x * BM_TC;

    // ---- Stage A hi/lo: pure uint4 copy (64 rows x 16 uint4) ----
    for (int i = tid; i < BM_TC * 16; i += TC_T) {
        int row = i >> 4;
        int q   = i & 15;                 // uint4 index within row (8 bf16)
        int m   = m0 + row;
        uint4 vh = make_uint4(0, 0, 0, 0), vl = make_uint4(0, 0, 0, 0);
        if (m < N_NODES) {
            vh = __ldg((const uint4*)(Ah + (size_t)m * DIM) + q);
            vl = __ldg((const uint4*)(Al + (size_t)m * DIM) + q);
        }
        uint32_t boff = (uint32_t)(row * LDA + q * 8) * 2u;
        *(uint4*)(smc + SM_AH + boff) = vh;
        *(uint4*)(smc + SM_AL + boff) = vl;
    }
    // ---- Stage W hi/lo: pure uint4 copy (128 rows x 16 uint4) ----
    for (int i = tid; i < 128 * 16; i += TC_T) {
        int row = i >> 4;
        int q   = i & 15;
        uint4 vh = __ldg((const uint4*)(Wh + (size_t)row * DIM) + q);
        uint4 vl = __ldg((const uint4*)(Wl + (size_t)row * DIM) + q);
        uint32_t boff = (uint32_t)(row * LDA + q * 8) * 2u;
        *(uint4*)(smc + SM_WH + boff) = vh;
        *(uint4*)(smc + SM_WL + boff) = vl;
    }
    __syncthreads();

    // ---- Warp tiling: 2(m) x 8(n); warp tile 32 rows x 16 cols ----
    const int wm = wid & 1;
    const int wn = wid >> 1;

    const int a_row = (lane & 7) + (lane & 8);
    const int a_col = (lane >> 4) * 8;
    const int b_row = (lane & 7);
    const int b_col = ((lane >> 3) & 1) * 8;

    float d[2][2][4];
    #pragma unroll
    for (int mt = 0; mt < 2; ++mt)
        #pragma unroll
        for (int nt = 0; nt < 2; ++nt)
            #pragma unroll
            for (int q = 0; q < 4; ++q) d[mt][nt][q] = 0.0f;

    #pragma unroll 1
    for (int pass = 0; pass < 3; ++pass) {
        const uint32_t abase = sbase + ((pass == 1) ? SM_AL : SM_AH);
        const uint32_t wbase = sbase + ((pass == 2) ? SM_WL : SM_WH);
        #pragma unroll 4
        for (int ks = 0; ks < 8; ++ks) {
            const int k0 = ks * 16;
            uint32_t af[2][4];
            #pragma unroll
            for (int mt = 0; mt < 2; ++mt) {
                uint32_t addr = abase +
                    (uint32_t)((wm * 32 + mt * 16 + a_row) * LDA + k0 + a_col) * 2u;
                ldsm_x4(af[mt], addr);
            }
            uint32_t bfr[2][2];
            #pragma unroll
            for (int nt = 0; nt < 2; ++nt) {
                uint32_t addr = wbase +
                    (uint32_t)((wn * 16 + nt * 8 + b_row) * LDA + k0 + b_col) * 2u;
                ldsm_x2(bfr[nt], addr);
            }
            #pragma unroll
            for (int mt = 0; mt < 2; ++mt)
                #pragma unroll
                for (int nt = 0; nt < 2; ++nt)
                    mma_bf16(d[mt][nt], af[mt], bfr[nt]);
        }
    }

    // ---- Epilogue ----
    const int colbase = wn * 16;
    #pragma unroll
    for (int nt = 0; nt < 2; ++nt) {
        int c = colbase + nt * 8 + (lane & 3) * 2;
        float2 bs = __ldg((const float2*)&Bias[c]);
        #pragma unroll
        for (int mt = 0; mt < 2; ++mt) {
            const float* dd = d[mt][nt];
            #pragma unroll
            for (int half = 0; half < 2; ++half) {
                int r = m0 + wm * 32 + mt * 16 + (lane >> 2) + half * 8;
                if (r < N_NODES) {
                    float v0 = dd[half * 2 + 0] + bs.x;
                    float v1 = dd[half * 2 + 1] + bs.y;
                    if (LEAKY) {
                        v0 = (v0 >= 0.0f) ? v0 : 0.01f * v0;
                        v1 = (v1 >= 0.0f) ? v1 : 0.01f * v1;
                    }
                    if (SPLIT_OUT) {
                        uint32_t hi2, lo2;
                        split2(v0, v1, hi2, lo2);
                        *(uint32_t*)(OUTh + (size_t)r * DIM + c) = hi2;
                        *(uint32_t*)(OUTl + (size_t)r * DIM + c) = lo2;
                    } else {
                        *(float2*)(OUT + (size_t)r * DIM + c) = make_float2(v0, v1);
                    }
                }
            }
        }
    }
}

// ---------------------------------------------------------------------------
// Launcher — order: histscan(0), fill(1), agg(2), gemm1(3) <- ncu, gemm2(4)
// ---------------------------------------------------------------------------
extern "C" void kernel_launch(void* const* d_in, const int* in_sizes, int n_in,
                              void* d_out, int out_size) {
    const float* x   = (const float*)d_in[0];
    const int*   ei  = (const int*)d_in[1];
    const float* ew  = (const float*)d_in[2];
    const float* w1  = (const float*)d_in[3];
    const float* b1  = (const float*)d_in[4];
    const float* w2  = (const float*)d_in[5];
    const float* b2  = (const float*)d_in[6];
    const float* eps = (const float*)d_in[7];
    float*       out = (float*)d_out;

    cudaFuncSetAttribute(mlp_gemm_mma_kernel<true, true>,
                         cudaFuncAttributeMaxDynamicSharedMemorySize, SMEM_TC);
    cudaFuncSetAttribute(mlp_gemm_mma_kernel<false, false>,
                         cudaFuncAttributeMaxDynamicSharedMemorySize, SMEM_TC);

    void *p_w1h, *p_w1l, *p_w2h, *p_w2l, *p_ah, *p_al, *p_hh, *p_hl;
    cudaGetSymbolAddress(&p_w1h, g_w1h);
    cudaGetSymbolAddress(&p_w1l, g_w1l);
    cudaGetSymbolAddress(&p_w2h, g_w2h);
    cudaGetSymbolAddress(&p_w2l, g_w2l);
    cudaGetSymbolAddress(&p_ah,  g_ah);
    cudaGetSymbolAddress(&p_al,  g_al);
    cudaGetSymbolAddress(&p_hh,  g_hh);
    cudaGetSymbolAddress(&p_hl,  g_hl);

    histscan_kernel<<<SCAN_B, SCAN_T>>>(ei, w1, w2);                 // 0
    fill_kernel<<<(E_EDGES + 255) / 256, 256>>>(ei, ew);             // 1
    agg_kernel<<<(N_NODES * 32 + 255) / 256, 256>>>(x, eps);         // 2

    {
        int blocks = (N_NODES + BM_TC - 1) / BM_TC;
        mlp_gemm_mma_kernel<true, true><<<blocks, TC_T, SMEM_TC>>>(  // 3 <- ncu
            (const __nv_bfloat16*)p_ah, (const __nv_bfloat16*)p_al,
            (const __nv_bfloat16*)p_w1h, (const __nv_bfloat16*)p_w1l,
            b1, nullptr,
            (__nv_bfloat16*)p_hh, (__nv_bfloat16*)p_hl);
        mlp_gemm_mma_kernel<false, false><<<blocks, TC_T, SMEM_TC>>>( // 4
            (const __nv_bfloat16*)p_hh, (const __nv_bfloat16*)p_hl,
            (const __nv_bfloat16*)p_w2h, (const __nv_bfloat16*)p_w2l,
            b2, out, nullptr, nullptr);
    }
}

// round 17
// speedup vs baseline: 1.1418x; 1.0730x over previous
#include <cuda_runtime.h>
#include <cuda_bf16.h>
#include <cstdint>

#define N_NODES 50000
#define E_EDGES 800000
#define DIM 128
#define NEG_INF_F __int_as_float(0xff800000)

#define SCAN_B 49
#define SCAN_T 1024
#define HIST_PER_T 16

// ---------------------------------------------------------------------------
// Static device scratch (zero-restored each call; graph-replay deterministic)
// ---------------------------------------------------------------------------
__device__ int   g_is64;
__device__ int   g_cnt[N_NODES];
__device__ int   g_row[N_NODES + 1];
__device__ int   g_cur[N_NODES];
__device__ int   g_blksum[SCAN_B];
__device__ int   g_done1;
__device__ int   g_done2;
__device__ int2  g_edge[E_EDGES];

// bf16 hi/lo operands (produced once per call; GEMMs do pure copies)
__device__ __nv_bfloat16 g_w1h[DIM * DIM], g_w1l[DIM * DIM];
__device__ __nv_bfloat16 g_w2h[DIM * DIM], g_w2l[DIM * DIM];
__device__ __nv_bfloat16 g_ah[(size_t)N_NODES * DIM], g_al[(size_t)N_NODES * DIM];
__device__ __nv_bfloat16 g_hh[(size_t)N_NODES * DIM], g_hl[(size_t)N_NODES * DIM];

// split fp32 pair -> packed bf16x2 hi and lo (residual)
__device__ __forceinline__ void split2(float v0, float v1,
                                       uint32_t& hi2, uint32_t& lo2) {
    __nv_bfloat16 h0 = __float2bfloat16_rn(v0);
    __nv_bfloat16 h1 = __float2bfloat16_rn(v1);
    __nv_bfloat16 l0 = __float2bfloat16_rn(v0 - __bfloat162float(h0));
    __nv_bfloat16 l1 = __float2bfloat16_rn(v1 - __bfloat162float(h1));
    hi2 = (uint32_t)__bfloat16_as_ushort(h0) |
          ((uint32_t)__bfloat16_as_ushort(h1) << 16);
    lo2 = (uint32_t)__bfloat16_as_ushort(l0) |
          ((uint32_t)__bfloat16_as_ushort(l1) << 16);
}

// ---------------------------------------------------------------------------
// Kernel 0: fused histogram + exclusive scan + W bf16-split
// ---------------------------------------------------------------------------
__global__ void __launch_bounds__(SCAN_T, 1)
histscan_kernel(const int* __restrict__ ei32,
                const float* __restrict__ w1,
                const float* __restrict__ w2) {
    __shared__ int sh[SCAN_T];
    __shared__ int pre[SCAN_B];
    __shared__ int offset;
    __shared__ int any_nonzero;
    __shared__ int bar_ok;

    int t = threadIdx.x;
    int b = blockIdx.x;

    // --- W split (one elem per thread; 32768 < 49*1024) ---
    {
        int g = b * SCAN_T + t;
        if (g < DIM * DIM) {
            float v = __ldg(&w1[g]);
            __nv_bfloat16 h = __float2bfloat16_rn(v);
            g_w1h[g] = h;
            g_w1l[g] = __float2bfloat16_rn(v - __bfloat162float(h));
        } else if (g < 2 * DIM * DIM) {
            int q = g - DIM * DIM;
            float v = __ldg(&w2[q]);
            __nv_bfloat16 h = __float2bfloat16_rn(v);
            g_w2h[q] = h;
            g_w2l[q] = __float2bfloat16_rn(v - __bfloat162float(h));
        }
    }

    if (t == 0) any_nonzero = 0;
    __syncthreads();
    if (t < 256) {
        int k = t * 3000;
        if (ei32[2 * k + 1] != 0) atomicOr(&any_nonzero, 1);
    }
    __syncthreads();
    int is64 = any_nonzero ? 0 : 1;
    if (b == 0 && t == 0) g_is64 = is64;

    const long long* e64 = (const long long*)ei32;
    #pragma unroll
    for (int i = 0; i < HIST_PER_T; ++i) {
        int e = b * SCAN_T + t + i * (SCAN_B * SCAN_T);
        if (e < E_EDGES) {
            int src, dst;
            if (is64) {
                src = (int)e64[e];
                dst = (int)e64[(size_t)E_EDGES + e];
            } else {
                src = ei32[e];
                dst = ei32[(size_t)E_EDGES + e];
            }
            if ((unsigned)src < N_NODES && (unsigned)dst < N_NODES)
                atomicAdd(&g_cnt[dst], 1);
        }
    }

    __threadfence();
    __syncthreads();
    if (t == 0) {
        atomicAdd(&g_done1, 1);
        while (((volatile int*)&g_done1)[0] < SCAN_B) { }
        bar_ok = 1;
    }
    __syncthreads();
    (void)bar_ok;
    __threadfence();

    int idx = b * SCAN_T + t;
    int c = (idx < N_NODES) ? g_cnt[idx] : 0;
    if (idx < N_NODES) g_cnt[idx] = 0;
    sh[t] = c;
    __syncthreads();
    #pragma unroll
    for (int off = 1; off < SCAN_T; off <<= 1) {
        int v = (t >= off) ? sh[t - off] : 0;
        __syncthreads();
        sh[t] += v;
        __syncthreads();
    }
    int ex = sh[t] - c;
    if (t == SCAN_T - 1)
        ((volatile int*)g_blksum)[b] = sh[t] + 1;

    if (t < SCAN_B) {
        int v;
        do { v = ((volatile int*)g_blksum)[t]; } while (v == 0);
        pre[t] = v - 1;
    }
    __syncthreads();
    if (t == 0) {
        int s = 0;
        for (int i = 0; i < b; ++i) s += pre[i];
        offset = s;
    }
    __syncthreads();

    if (idx <= N_NODES) g_row[idx] = ex + offset;
    if (idx < N_NODES)  g_cur[idx] = 0;

    if (t == 0) {
        int old = atomicAdd(&g_done2, 1);
        if (old == SCAN_B - 1) {
            for (int i = 0; i < SCAN_B; ++i) g_blksum[i] = 0;
            g_done1 = 0;
            g_done2 = 0;
        }
    }
}

// ---------------------------------------------------------------------------
// Kernel 1: bucket edges by dst (unchanged)
// ---------------------------------------------------------------------------
__global__ void fill_kernel(const int* __restrict__ ei32,
                            const float* __restrict__ ew) {
    int e = blockIdx.x * blockDim.x + threadIdx.x;
    if (e >= E_EDGES) return;
    int src, dst;
    if (g_is64) {
        const long long* e64 = (const long long*)ei32;
        src = (int)e64[e];
        dst = (int)e64[(size_t)E_EDGES + e];
    } else {
        src = ei32[e];
        dst = ei32[(size_t)E_EDGES + e];
    }
    if ((unsigned)src >= N_NODES || (unsigned)dst >= N_NODES) return;
    int pos = g_row[dst] + atomicAdd(&g_cur[dst], 1);
    g_edge[pos] = make_int2(src, __float_as_int(ew[e]));
}

// ---------------------------------------------------------------------------
// Kernel 2: aggregate + fuse; emits GEMM1 input as bf16 hi/lo. (unchanged)
// ---------------------------------------------------------------------------
__device__ __forceinline__ float4 max4w(float4 a, float4 v, float w) {
    a.x = fmaxf(a.x, v.x * w);
    a.y = fmaxf(a.y, v.y * w);
    a.z = fmaxf(a.z, v.z * w);
    a.w = fmaxf(a.w, v.w * w);
    return a;
}

__global__ void agg_kernel(const float* __restrict__ x,
                           const float* __restrict__ eps) {
    int warp = (blockIdx.x * blockDim.x + threadIdx.x) >> 5;
    if (warp >= N_NODES) return;
    int lane = threadIdx.x & 31;
    int beg = __ldg(&g_row[warp]);
    int end = __ldg(&g_row[warp + 1]);

    float4 acc = make_float4(NEG_INF_F, NEG_INF_F, NEG_INF_F, NEG_INF_F);
    int j = beg;
    for (; j + 8 <= end; j += 8) {
        int2 e[8];
        #pragma unroll
        for (int i = 0; i < 8; ++i) e[i] = __ldg(&g_edge[j + i]);
        float4 v[8];
        #pragma unroll
        for (int i = 0; i < 8; ++i)
            v[i] = __ldg(&((const float4*)(x + (size_t)e[i].x * DIM))[lane]);
        #pragma unroll
        for (int i = 0; i < 8; ++i)
            acc = max4w(acc, v[i], __int_as_float(e[i].y));
    }
    if (j + 4 <= end) {
        int2 e[4];
        #pragma unroll
        for (int i = 0; i < 4; ++i) e[i] = __ldg(&g_edge[j + i]);
        float4 v[4];
        #pragma unroll
        for (int i = 0; i < 4; ++i)
            v[i] = __ldg(&((const float4*)(x + (size_t)e[i].x * DIM))[lane]);
        #pragma unroll
        for (int i = 0; i < 4; ++i)
            acc = max4w(acc, v[i], __int_as_float(e[i].y));
        j += 4;
    }
    for (; j < end; ++j) {
        int2 ep = __ldg(&g_edge[j]);
        float4 v = __ldg(&((const float4*)(x + (size_t)ep.x * DIM))[lane]);
        acc = max4w(acc, v, __int_as_float(ep.y));
    }
    if (beg == end) acc = make_float4(0.f, 0.f, 0.f, 0.f);

    float s = 1.0f + __ldg(eps);
    float4 xv = __ldg(&((const float4*)(x + (size_t)warp * DIM))[lane]);
    acc.x = fmaf(s, xv.x, acc.x);
    acc.y = fmaf(s, xv.y, acc.y);
    acc.z = fmaf(s, xv.z, acc.z);
    acc.w = fmaf(s, xv.w, acc.w);

    uint32_t h01, l01, h23, l23;
    split2(acc.x, acc.y, h01, l01);
    split2(acc.z, acc.w, h23, l23);
    size_t base = (size_t)warp * DIM + lane * 4;
    *(uint2*)(g_ah + base) = make_uint2(h01, h23);
    *(uint2*)(g_al + base) = make_uint2(l01, l23);
}

// ---------------------------------------------------------------------------
// Tensor-core GEMM via mma.sync (HMMA). OUT = act(A @ W^T + Bias).
// Operands pre-split bf16 hi/lo in global; staging = pure uint4 copy.
// FUSED single k-loop: per k-step load Ah,Al (ldsm x4) + Wh,Wl (ldsm x2)
// ONCE and issue the 3 split-term MMA groups -> 4 tile-loads/k-step vs 6.
// CTA: 64x128 tile, 512 threads, warp grid 2(m) x 8(n); warp tile 32x16.
// Smem 104448 B -> 2 CTA/SM. LDA=136 padding -> conflict-free ldmatrix.
// ---------------------------------------------------------------------------
#define TC_T 512
#define BM_TC 64
#define LDA 136
#define A_TILE_B (BM_TC * LDA * 2)    // 17408 B
#define W_TILE_B (128 * LDA * 2)      // 34816 B
#define SM_AH 0
#define SM_AL (A_TILE_B)
#define SM_WH (2 * A_TILE_B)
#define SM_WL (2 * A_TILE_B + W_TILE_B)
#define SMEM_TC (2 * A_TILE_B + 2 * W_TILE_B)   // 104448 B

__device__ __forceinline__ uint32_t smem_u32(const void* p) {
    uint32_t a;
    asm("{ .reg .u64 t; cvta.to.shared.u64 t, %1; cvt.u32.u64 %0, t; }"
        : "=r"(a) : "l"(p));
    return a;
}
__device__ __forceinline__ void ldsm_x4(uint32_t* r, uint32_t addr) {
    asm volatile("ldmatrix.sync.aligned.m8n8.x4.shared.b16 {%0,%1,%2,%3}, [%4];"
                 : "=r"(r[0]), "=r"(r[1]), "=r"(r[2]), "=r"(r[3]) : "r"(addr));
}
__device__ __forceinline__ void ldsm_x2(uint32_t* r, uint32_t addr) {
    asm volatile("ldmatrix.sync.aligned.m8n8.x2.shared.b16 {%0,%1}, [%2];"
                 : "=r"(r[0]), "=r"(r[1]) : "r"(addr));
}
__device__ __forceinline__ void mma_bf16(float* d, const uint32_t* a,
                                         const uint32_t* b) {
    asm volatile(
        "mma.sync.aligned.m16n8k16.row.col.f32.bf16.bf16.f32 "
        "{%0,%1,%2,%3}, {%4,%5,%6,%7}, {%8,%9}, {%0,%1,%2,%3};"
        : "+f"(d[0]), "+f"(d[1]), "+f"(d[2]), "+f"(d[3])
        : "r"(a[0]), "r"(a[1]), "r"(a[2]), "r"(a[3]), "r"(b[0]), "r"(b[1]));
}

template <bool LEAKY, bool SPLIT_OUT>
__global__ void __launch_bounds__(TC_T, 2)
mlp_gemm_mma_kernel(const __nv_bfloat16* __restrict__ Ah,
                    const __nv_bfloat16* __restrict__ Al,
                    const __nv_bfloat16* __restrict__ Wh,
                    const __nv_bfloat16* __restrict__ Wl,
                    const float* __restrict__ Bias,
                    float* __restrict__ OUT,
                    __nv_bfloat16* __restrict__ OUTh,
                    __nv_bfloat16* __restrict__ OUTl) {
    extern __shared__ char smc[];
    const uint32_t sbase = smem_u32(smc);
    const int tid  = threadIdx.x;
    const int wid  = tid >> 5;
    const int lane = tid & 31;
    const int m0   = blockIdx.x * BM_TC;

    // ---- Stage A hi/lo: pure uint4 copy (64 rows x 16 uint4) ----
    for (int i = tid; i < BM_TC * 16; i += TC_T) {
        int row = i >> 4;
        int q   = i & 15;
        int m   = m0 + row;
        uint4 vh = make_uint4(0, 0, 0, 0), vl = make_uint4(0, 0, 0, 0);
        if (m < N_NODES) {
            vh = __ldg((const uint4*)(Ah + (size_t)m * DIM) + q);
            vl = __ldg((const uint4*)(Al + (size_t)m * DIM) + q);
        }
        uint32_t boff = (uint32_t)(row * LDA + q * 8) * 2u;
        *(uint4*)(smc + SM_AH + boff) = vh;
        *(uint4*)(smc + SM_AL + boff) = vl;
    }
    // ---- Stage W hi/lo: pure uint4 copy (128 rows x 16 uint4) ----
    for (int i = tid; i < 128 * 16; i += TC_T) {
        int row = i >> 4;
        int q   = i & 15;
        uint4 vh = __ldg((const uint4*)(Wh + (size_t)row * DIM) + q);
        uint4 vl = __ldg((const uint4*)(Wl + (size_t)row * DIM) + q);
        uint32_t boff = (uint32_t)(row * LDA + q * 8) * 2u;
        *(uint4*)(smc + SM_WH + boff) = vh;
        *(uint4*)(smc + SM_WL + boff) = vl;
    }
    __syncthreads();

    // ---- Warp tiling: 2(m) x 8(n); warp tile 32 rows x 16 cols ----
    const int wm = wid & 1;
    const int wn = wid >> 1;

    const int a_row = (lane & 7) + (lane & 8);
    const int a_col = (lane >> 4) * 8;
    const int b_row = (lane & 7);
    const int b_col = ((lane >> 3) & 1) * 8;

    float d[2][2][4];
    #pragma unroll
    for (int mt = 0; mt < 2; ++mt)
        #pragma unroll
        for (int nt = 0; nt < 2; ++nt)
            #pragma unroll
            for (int q = 0; q < 4; ++q) d[mt][nt][q] = 0.0f;

    // ---- FUSED mainloop: each fragment loaded once per k-step ----
    #pragma unroll 2
    for (int ks = 0; ks < 8; ++ks) {
        const int k0 = ks * 16;
        uint32_t afh[2][4], afl[2][4];
        #pragma unroll
        for (int mt = 0; mt < 2; ++mt) {
            uint32_t roff =
                (uint32_t)((wm * 32 + mt * 16 + a_row) * LDA + k0 + a_col) * 2u;
            ldsm_x4(afh[mt], sbase + SM_AH + roff);
            ldsm_x4(afl[mt], sbase + SM_AL + roff);
        }
        uint32_t bfh[2][2], bfl[2][2];
        #pragma unroll
        for (int nt = 0; nt < 2; ++nt) {
            uint32_t roff =
                (uint32_t)((wn * 16 + nt * 8 + b_row) * LDA + k0 + b_col) * 2u;
            ldsm_x2(bfh[nt], sbase + SM_WH + roff);
            ldsm_x2(bfl[nt], sbase + SM_WL + roff);
        }
        #pragma unroll
        for (int mt = 0; mt < 2; ++mt)
            #pragma unroll
            for (int nt = 0; nt < 2; ++nt) {
                mma_bf16(d[mt][nt], afh[mt], bfh[nt]);   // Ah*Wh
                mma_bf16(d[mt][nt], afl[mt], bfh[nt]);   // Al*Wh
                mma_bf16(d[mt][nt], afh[mt], bfl[nt]);   // Ah*Wl
            }
    }

    // ---- Epilogue ----
    const int colbase = wn * 16;
    #pragma unroll
    for (int nt = 0; nt < 2; ++nt) {
        int c = colbase + nt * 8 + (lane & 3) * 2;
        float2 bs = __ldg((const float2*)&Bias[c]);
        #pragma unroll
        for (int mt = 0; mt < 2; ++mt) {
            const float* dd = d[mt][nt];
            #pragma unroll
            for (int half = 0; half < 2; ++half) {
                int r = m0 + wm * 32 + mt * 16 + (lane >> 2) + half * 8;
                if (r < N_NODES) {
                    float v0 = dd[half * 2 + 0] + bs.x;
                    float v1 = dd[half * 2 + 1] + bs.y;
                    if (LEAKY) {
                        v0 = (v0 >= 0.0f) ? v0 : 0.01f * v0;
                        v1 = (v1 >= 0.0f) ? v1 : 0.01f * v1;
                    }
                    if (SPLIT_OUT) {
                        uint32_t hi2, lo2;
                        split2(v0, v1, hi2, lo2);
                        *(uint32_t*)(OUTh + (size_t)r * DIM + c) = hi2;
                        *(uint32_t*)(OUTl + (size_t)r * DIM + c) = lo2;
                    } else {
                        *(float2*)(OUT + (size_t)r * DIM + c) = make_float2(v0, v1);
                    }
                }
            }
        }
    }
}

// ---------------------------------------------------------------------------
// Launcher — order: histscan(0), fill(1), agg(2), gemm1(3) <- ncu, gemm2(4)
// ---------------------------------------------------------------------------
extern "C" void kernel_launch(void* const* d_in, const int* in_sizes, int n_in,
                              void* d_out, int out_size) {
    const float* x   = (const float*)d_in[0];
    const int*   ei  = (const int*)d_in[1];
    const float* ew  = (const float*)d_in[2];
    const float* w1  = (const float*)d_in[3];
    const float* b1  = (const float*)d_in[4];
    const float* w2  = (const float*)d_in[5];
    const float* b2  = (const float*)d_in[6];
    const float* eps = (const float*)d_in[7];
    float*       out = (float*)d_out;

    cudaFuncSetAttribute(mlp_gemm_mma_kernel<true, true>,
                         cudaFuncAttributeMaxDynamicSharedMemorySize, SMEM_TC);
    cudaFuncSetAttribute(mlp_gemm_mma_kernel<false, false>,
                         cudaFuncAttributeMaxDynamicSharedMemorySize, SMEM_TC);

    void *p_w1h, *p_w1l, *p_w2h, *p_w2l, *p_ah, *p_al, *p_hh, *p_hl;
    cudaGetSymbolAddress(&p_w1h, g_w1h);
    cudaGetSymbolAddress(&p_w1l, g_w1l);
    cudaGetSymbolAddress(&p_w2h, g_w2h);
    cudaGetSymbolAddress(&p_w2l, g_w2l);
    cudaGetSymbolAddress(&p_ah,  g_ah);
    cudaGetSymbolAddress(&p_al,  g_al);
    cudaGetSymbolAddress(&p_hh,  g_hh);
    cudaGetSymbolAddress(&p_hl,  g_hl);

    histscan_kernel<<<SCAN_B, SCAN_T>>>(ei, w1, w2);                 // 0
    fill_kernel<<<(E_EDGES + 255) / 256, 256>>>(ei, ew);             // 1
    agg_kernel<<<(N_NODES * 32 + 255) / 256, 256>>>(x, eps);         // 2

    {
        int blocks = (N_NODES + BM_TC - 1) / BM_TC;
        mlp_gemm_mma_kernel<true, true><<<blocks, TC_T, SMEM_TC>>>(  // 3 <- ncu
            (const __nv_bfloat16*)p_ah, (const __nv_bfloat16*)p_al,
            (const __nv_bfloat16*)p_w1h, (const __nv_bfloat16*)p_w1l,
            b1, nullptr,
            (__nv_bfloat16*)p_hh, (__nv_bfloat16*)p_hl);
        mlp_gemm_mma_kernel<false, false><<<blocks, TC_T, SMEM_TC>>>( // 4
            (const __nv_bfloat16*)p_hh, (const __nv_bfloat16*)p_hl,
            (const __nv_bfloat16*)p_w2h, (const __nv_bfloat16*)p_w2l,
            b2, out, nullptr, nullptr);
    }
}